// round 8
// baseline (speedup 1.0000x reference)
#include <cuda_runtime.h>

#define TT 1024
#define BBATCH 32
#define DD 1024
#define GCTA 128
#define NTH 256

__device__ float g_Y[(size_t)TT * BBATCH * 3072];      // ax|bx|wx interleaved
__device__ float g_H[(size_t)(TT + 1) * BBATCH * DD];  // fallback h chain
__device__ unsigned g_count;
__device__ unsigned g_release;

__device__ __forceinline__ unsigned long long pk2(float x, float y) {
    unsigned long long r;
    asm("mov.b64 %0, {%1, %2};" : "=l"(r) : "f"(x), "f"(y));
    return r;
}
__device__ __forceinline__ void fma2(unsigned long long& d, unsigned long long a,
                                     unsigned long long b) {
    asm("fma.rn.f32x2 %0, %1, %2, %0;" : "+l"(d) : "l"(a), "l"(b));
}
__device__ __forceinline__ void up2(unsigned long long v, float& x, float& y) {
    asm("mov.b64 {%0, %1}, %2;" : "=f"(x), "=f"(y) : "l"(v));
}
__device__ __forceinline__ float sgm(float z) {
    return __fdividef(1.0f, 1.0f + __expf(-z));
}
__device__ __forceinline__ float tnh(float z) {
    return __fdividef(2.0f, 1.0f + __expf(-2.0f * z)) - 1.0f;
}

__global__ void reset_kernel(float* __restrict__ hbase) {
    unsigned i = blockIdx.x * blockDim.x + threadIdx.x;  // 32768 = B*D
    hbase[i] = 0.0f;
    if (i == 0) { g_count = 0u; g_release = 0u; }
}

// Y[m][n] = sum_k X[m][k] * Wrow[n][k].  grid = (24, 256), 256 threads.
__global__ void __launch_bounds__(256) gemm_kernel(const float* __restrict__ X,
                                                   const float* __restrict__ Wa,
                                                   const float* __restrict__ Wb,
                                                   const float* __restrict__ Wx) {
    __shared__ __align__(16) float As[8][128];
    __shared__ __align__(16) float Bs[8][128];
    const int bn = blockIdx.x, bm = blockIdx.y, tid = threadIdx.x;
    const int tx = tid & 15, ty = tid >> 4;
    const float* Wsrc = (bn < 8) ? Wa : (bn < 16) ? Wb : Wx;
    const int nloc = (bn & 7) * 128;
    const int row = tid >> 1, cg = (tid & 1) * 4;

    unsigned long long acc2[8][4];
#pragma unroll
    for (int i = 0; i < 8; ++i)
#pragma unroll
        for (int j = 0; j < 4; ++j) acc2[i][j] = 0ull;

    for (int k0 = 0; k0 < 1024; k0 += 8) {
        float4 a = *(const float4*)(X + (size_t)(bm * 128 + row) * 1024 + k0 + cg);
        float4 b = *(const float4*)(Wsrc + (size_t)(nloc + row) * 1024 + k0 + cg);
        As[cg + 0][row] = a.x; As[cg + 1][row] = a.y;
        As[cg + 2][row] = a.z; As[cg + 3][row] = a.w;
        Bs[cg + 0][row] = b.x; Bs[cg + 1][row] = b.y;
        Bs[cg + 2][row] = b.z; Bs[cg + 3][row] = b.w;
        __syncthreads();
#pragma unroll
        for (int kk = 0; kk < 8; ++kk) {
            float4 av0 = *(const float4*)&As[kk][ty * 8];
            float4 av1 = *(const float4*)&As[kk][ty * 8 + 4];
            float4 bv0 = *(const float4*)&Bs[kk][tx * 8];
            float4 bv1 = *(const float4*)&Bs[kk][tx * 8 + 4];
            unsigned long long bd[4] = {pk2(bv0.x, bv0.y), pk2(bv0.z, bv0.w),
                                        pk2(bv1.x, bv1.y), pk2(bv1.z, bv1.w)};
            float av[8] = {av0.x, av0.y, av0.z, av0.w, av1.x, av1.y, av1.z, av1.w};
#pragma unroll
            for (int i = 0; i < 8; ++i) {
                unsigned long long ad = pk2(av[i], av[i]);
#pragma unroll
                for (int j = 0; j < 4; ++j) fma2(acc2[i][j], ad, bd[j]);
            }
        }
        __syncthreads();
    }
#pragma unroll
    for (int i = 0; i < 8; ++i) {
        float o[8];
#pragma unroll
        for (int j = 0; j < 4; ++j) up2(acc2[i][j], o[2 * j], o[2 * j + 1]);
        size_t m = (size_t)bm * 128 + ty * 8 + i;
        float* dst = g_Y + m * 3072 + bn * 128 + tx * 8;
        *(float4*)dst = make_float4(o[0], o[1], o[2], o[3]);
        *(float4*)(dst + 4) = make_float4(o[4], o[5], o[6], o[7]);
    }
}

// Persistent recurrence. CTA owns features [e0, e0+8) of Ua/Ub/Wh (96 KB SMEM).
__global__ void __launch_bounds__(NTH, 1) recur_kernel(
    const float* __restrict__ Ua, const float* __restrict__ Ub,
    const float* __restrict__ Wh, const float* __restrict__ p_ba,
    const float* __restrict__ p_bb, const float* __restrict__ p_bv,
    float* __restrict__ outp, float* __restrict__ hbase) {
    extern __shared__ float4 ws4[];  // 24 rows * 256 float4 = 96 KB
    __shared__ float Psm[32][24];    // [batch][row]

    const int tid = threadIdx.x;
    const int lane = tid & 31, wid = tid >> 5;
    const int e0 = blockIdx.x * 8;

    for (int idx = tid; idx < 24 * 256; idx += NTH) {
        int r = idx >> 8, c = idx & 255;
        const float* src = (r < 8) ? Ua + (size_t)(e0 + r) * DD
                         : (r < 16) ? Ub + (size_t)(e0 + r - 8) * DD
                                    : Wh + (size_t)(e0 + r - 16) * DD;
        ws4[idx] = ((const float4*)src)[c];
    }
    const int eb = tid & 7;   // epilogue feature
    const int bi = tid >> 3;  // epilogue batch
    const float rba = p_ba[e0 + eb];
    const float rbb = p_bb[e0 + eb];
    const float rbv = p_bv[e0 + eb];
    __syncthreads();

#pragma unroll 1
    for (int t = 0; t < TT; ++t) {
        const float* hp = hbase + (size_t)t * (BBATCH * DD);

        float4 h4[4][8];  // 4 batches x 32 floats/lane, interleaved+coalesced
#pragma unroll
        for (int b4 = 0; b4 < 4; ++b4) {
            const float* hb = hp + (size_t)(wid * 4 + b4) * DD + lane * 4;
#pragma unroll
            for (int i = 0; i < 8; ++i) h4[b4][i] = *(const float4*)(hb + i * 128);
        }

#pragma unroll 1
        for (int r = 0; r < 24; ++r) {
            float4 w4[8];
#pragma unroll
            for (int i = 0; i < 8; ++i) w4[i] = ws4[r * 256 + lane + 32 * i];
#pragma unroll
            for (int b4 = 0; b4 < 4; ++b4) {
                unsigned long long a01 = 0ull, a23 = 0ull;
#pragma unroll
                for (int i = 0; i < 8; ++i) {
                    fma2(a01, pk2(h4[b4][i].x, h4[b4][i].y), pk2(w4[i].x, w4[i].y));
                    fma2(a23, pk2(h4[b4][i].z, h4[b4][i].w), pk2(w4[i].z, w4[i].w));
                }
                float p0, p1, q0, q1;
                up2(a01, p0, p1);
                up2(a23, q0, q1);
                float s = (p0 + p1) + (q0 + q1);
#pragma unroll
                for (int off = 16; off; off >>= 1)
                    s += __shfl_xor_sync(0xffffffffu, s, off);
                if (lane == 0) Psm[wid * 4 + b4][r] = s;
            }
        }
        __syncthreads();

        {   // fused gate epilogue: thread -> (batch bi, feature e0+eb)
            size_t ybase = ((size_t)t * BBATCH + bi) * 3072 + e0 + eb;
            float pa = Psm[bi][eb] + g_Y[ybase] + rba;
            float pb = Psm[bi][8 + eb] + g_Y[ybase + 1024] + rbb;
            float pv = Psm[bi][16 + eb] + g_Y[ybase + 2048] + rbv;
            float hv = hp[(size_t)bi * DD + e0 + eb];
            float al = sgm(pa);
            float be = sgm(pb);
            float v = tnh(pv);
            float hn = al * hv + be * v;
            float o = hn * hn * sgm(hn);  // h * silu(h)
            size_t oidx = (size_t)t * (BBATCH * DD) + (size_t)bi * DD + e0 + eb;
            outp[oidx] = o;
            hbase[oidx + BBATCH * DD] = hn;  // h[t+1]
        }
        if (t == TT - 1) break;

        __threadfence();
        __syncthreads();
        if (tid == 0) {
            unsigned arrived = atomicAdd(&g_count, 1u) + 1u;
            unsigned want = (unsigned)(t + 1) * (unsigned)GCTA;
            if (arrived == want) atomicExch(&g_release, (unsigned)(t + 1));
            while (*((volatile unsigned*)&g_release) < (unsigned)(t + 1))
                __nanosleep(64);
            __threadfence();
        }
        __syncthreads();
    }
}

extern "C" void kernel_launch(void* const* d_in, const int* in_sizes, int n_in,
                              void* d_out, int out_size) {
    (void)in_sizes; (void)n_in;
    const float* x  = (const float*)d_in[0];
    const float* Wa = (const float*)d_in[1];
    const float* Ua = (const float*)d_in[2];
    const float* ba = (const float*)d_in[3];
    const float* Wb = (const float*)d_in[4];
    const float* Ub = (const float*)d_in[5];
    const float* bb = (const float*)d_in[6];
    const float* Wh = (const float*)d_in[7];
    const float* Wx = (const float*)d_in[8];
    const float* bv = (const float*)d_in[9];
    float* outp = (float*)d_out;

    // Output may be outputs(T,B,D) ++ h(T+1,B,D), or outputs only.
    const long long need =
        (long long)TT * BBATCH * DD + (long long)(TT + 1) * BBATCH * DD;
    float* hbase;
    if ((long long)out_size >= need) {
        hbase = outp + (size_t)TT * BBATCH * DD;
    } else {
        void* p = nullptr;
        cudaGetSymbolAddress(&p, g_H);
        hbase = (float*)p;
    }

    cudaFuncSetAttribute(recur_kernel,
                         cudaFuncAttributeMaxDynamicSharedMemorySize, 98304);

    reset_kernel<<<128, 256>>>(hbase);
    dim3 gg(24, 256);
    gemm_kernel<<<gg, 256>>>(x, Wa, Wb, Wx);
    recur_kernel<<<GCTA, NTH, 98304>>>(Ua, Ub, Wh, ba, bb, bv, outp, hbase);
}